// round 4
// baseline (speedup 1.0000x reference)
#include <cuda_runtime.h>

// Problem constants
#define DZ 64
#define HH 512
#define WW 512
#define PAD 5            // window 11 -> half 5
#define TILE_H 64
#define NT 128           // threads per block
#define G 4              // columns per thread  (NT*G == WW)
#define ROWTILES (HH / TILE_H)   // 8
#define SH_W (WW + 2 * PAD + 2)  // 524, small pad

#define C1F 1.0e-4f      // 0.01^2
#define C2F 9.0e-4f      // 0.03^2

__device__ double g_accum;

__global__ void zero_accum_kernel() { g_accum = 0.0; }

__device__ __forceinline__ float ssim_from_sums(float sx, float sy, float sxx,
                                                float syy, float sxy, float wv) {
    float mx  = sx  * wv;
    float my  = sy  * wv;
    float ex2 = sxx * wv;
    float ey2 = syy * wv;
    float exy = sxy * wv;
    float mx2 = mx * mx;
    float my2 = my * my;
    float mxy = mx * my;
    float sgx  = ex2 - mx2;
    float sgy  = ey2 - my2;
    float sgxy = exy - mxy;
    float num = (2.0f * mxy + C1F) * (2.0f * sgxy + C2F);
    float den = (mx2 + my2 + C1F) * (sgx + sgy + C2F);
    return __fdividef(num, den);
}

__global__ __launch_bounds__(NT)
void ssim_kernel(const float* __restrict__ X, const float* __restrict__ Y,
                 const float* __restrict__ Wd) {
    // Double-buffered per-row exchange of vertical sums.
    // vsh4[b][idx] = (sum_x, sum_y, sum_x2, sum_y2) for column (idx-PAD)
    // vsh1[b][idx] = sum_xy
    __shared__ float4 vsh4[2][SH_W];
    __shared__ float  vsh1[2][SH_W];
    __shared__ float  redbuf[NT / 32];

    const int tid  = threadIdx.x;
    const int z    = blockIdx.x / ROWTILES;
    const int row0 = (blockIdx.x % ROWTILES) * TILE_H;

    const float* Xz = X + (size_t)z * HH * WW;
    const float* Yz = Y + (size_t)z * HH * WW;
    const float  wv = Wd[0];   // uniform window weight (1/121)

    // Zero the halo columns of both buffers once.
    if (tid < PAD) {
        #pragma unroll
        for (int b = 0; b < 2; ++b) {
            vsh4[b][tid]            = make_float4(0.f, 0.f, 0.f, 0.f);
            vsh1[b][tid]            = 0.f;
            vsh4[b][PAD + WW + tid] = make_float4(0.f, 0.f, 0.f, 0.f);
            vsh1[b][PAD + WW + tid] = 0.f;
        }
    }
    // (visibility guaranteed by the first __syncthreads inside the row loop)

    const int c0 = tid * G;   // first column owned by this thread

    // Vertical sliding sums for the 5 channels, 4 columns each (float4 lanes).
    float4 vs0 = make_float4(0.f, 0.f, 0.f, 0.f);  // sum x
    float4 vs1 = vs0;                              // sum y
    float4 vs2 = vs0;                              // sum x^2
    float4 vs3 = vs0;                              // sum y^2
    float4 vs4 = vs0;                              // sum x*y

    // Prologue: accumulate input rows [row0-5, row0+4]
    #pragma unroll 1
    for (int rr = row0 - PAD; rr < row0 + PAD; ++rr) {
        if (rr < 0 || rr >= HH) continue;
        float4 xv = *reinterpret_cast<const float4*>(Xz + rr * WW + c0);
        float4 yv = *reinterpret_cast<const float4*>(Yz + rr * WW + c0);
        vs0.x += xv.x; vs0.y += xv.y; vs0.z += xv.z; vs0.w += xv.w;
        vs1.x += yv.x; vs1.y += yv.y; vs1.z += yv.z; vs1.w += yv.w;
        vs2.x += xv.x*xv.x; vs2.y += xv.y*xv.y; vs2.z += xv.z*xv.z; vs2.w += xv.w*xv.w;
        vs3.x += yv.x*yv.x; vs3.y += yv.y*yv.y; vs3.z += yv.z*yv.z; vs3.w += yv.w*yv.w;
        vs4.x += xv.x*yv.x; vs4.y += xv.y*yv.y; vs4.z += xv.z*yv.z; vs4.w += xv.w*yv.w;
    }

    float partial = 0.0f;
    int buf = 0;

    #pragma unroll 1
    for (int r = row0; r < row0 + TILE_H; ++r, buf ^= 1) {
        // Slide vertical window: add row r+5; subtract row r-6, but ONLY if
        // that row was actually accumulated (the prologue starts at row0-5,
        // so at r == row0 nothing leaves the window).
        int rn = r + PAD;
        if (rn < HH) {
            float4 xv = *reinterpret_cast<const float4*>(Xz + rn * WW + c0);
            float4 yv = *reinterpret_cast<const float4*>(Yz + rn * WW + c0);
            vs0.x += xv.x; vs0.y += xv.y; vs0.z += xv.z; vs0.w += xv.w;
            vs1.x += yv.x; vs1.y += yv.y; vs1.z += yv.z; vs1.w += yv.w;
            vs2.x += xv.x*xv.x; vs2.y += xv.y*xv.y; vs2.z += xv.z*xv.z; vs2.w += xv.w*xv.w;
            vs3.x += yv.x*yv.x; vs3.y += yv.y*yv.y; vs3.z += yv.z*yv.z; vs3.w += yv.w*yv.w;
            vs4.x += xv.x*yv.x; vs4.y += xv.y*yv.y; vs4.z += xv.z*yv.z; vs4.w += xv.w*yv.w;
        }
        int ro = r - PAD - 1;
        if (r > row0 && ro >= 0) {
            float4 xv = *reinterpret_cast<const float4*>(Xz + ro * WW + c0);
            float4 yv = *reinterpret_cast<const float4*>(Yz + ro * WW + c0);
            vs0.x -= xv.x; vs0.y -= xv.y; vs0.z -= xv.z; vs0.w -= xv.w;
            vs1.x -= yv.x; vs1.y -= yv.y; vs1.z -= yv.z; vs1.w -= yv.w;
            vs2.x -= xv.x*xv.x; vs2.y -= xv.y*xv.y; vs2.z -= xv.z*xv.z; vs2.w -= xv.w*xv.w;
            vs3.x -= yv.x*yv.x; vs3.y -= yv.y*yv.y; vs3.z -= yv.z*yv.z; vs3.w -= yv.w*yv.w;
            vs4.x -= xv.x*yv.x; vs4.y -= xv.y*yv.y; vs4.z -= xv.z*yv.z; vs4.w -= xv.w*yv.w;
        }

        // Publish vertical sums (AoS transpose: per column float4 + float).
        int base = PAD + c0;
        vsh4[buf][base + 0] = make_float4(vs0.x, vs1.x, vs2.x, vs3.x);
        vsh1[buf][base + 0] = vs4.x;
        vsh4[buf][base + 1] = make_float4(vs0.y, vs1.y, vs2.y, vs3.y);
        vsh1[buf][base + 1] = vs4.y;
        vsh4[buf][base + 2] = make_float4(vs0.z, vs1.z, vs2.z, vs3.z);
        vsh1[buf][base + 2] = vs4.z;
        vsh4[buf][base + 3] = make_float4(vs0.w, vs1.w, vs2.w, vs3.w);
        vsh1[buf][base + 3] = vs4.w;

        __syncthreads();   // single barrier per row (double-buffered)

        // Horizontal 11-sum for column c0, then slide for c0+1..c0+3.
        // Column c is stored at index c+PAD, so output col c0 reads idx c0..c0+10.
        float4 h  = make_float4(0.f, 0.f, 0.f, 0.f);
        float  h1 = 0.f;
        float4 k4[3];
        float  k1[3];
        #pragma unroll
        for (int k = 0; k < 11; ++k) {
            float4 f  = vsh4[buf][c0 + k];
            float  f1 = vsh1[buf][c0 + k];
            if (k < 3) { k4[k] = f; k1[k] = f1; }
            h.x += f.x; h.y += f.y; h.z += f.z; h.w += f.w;
            h1  += f1;
        }
        partial += ssim_from_sums(h.x, h.y, h.z, h.w, h1, wv);

        #pragma unroll
        for (int g = 1; g < G; ++g) {
            float4 f  = vsh4[buf][c0 + 10 + g];
            float  f1 = vsh1[buf][c0 + 10 + g];
            h.x += f.x - k4[g - 1].x;
            h.y += f.y - k4[g - 1].y;
            h.z += f.z - k4[g - 1].z;
            h.w += f.w - k4[g - 1].w;
            h1  += f1  - k1[g - 1];
            partial += ssim_from_sums(h.x, h.y, h.z, h.w, h1, wv);
        }
        // no second barrier: next iteration writes the other buffer
    }

    // Block reduction of partial SSIM sums.
    #pragma unroll
    for (int off = 16; off > 0; off >>= 1)
        partial += __shfl_xor_sync(0xFFFFFFFFu, partial, off);
    if ((tid & 31) == 0) redbuf[tid >> 5] = partial;
    __syncthreads();
    if (tid == 0) {
        float s = redbuf[0] + redbuf[1] + redbuf[2] + redbuf[3];
        atomicAdd(&g_accum, (double)s);
    }
}

__global__ void finalize_kernel(float* out) {
    out[0] = (float)(1.0 - g_accum / (double)((size_t)DZ * HH * WW));
}

extern "C" void kernel_launch(void* const* d_in, const int* in_sizes, int n_in,
                              void* d_out, int out_size) {
    const float* x = (const float*)d_in[0];
    const float* y = (const float*)d_in[1];
    const float* w = (const float*)d_in[2];
    float* out = (float*)d_out;

    zero_accum_kernel<<<1, 1>>>();
    ssim_kernel<<<DZ * ROWTILES, NT>>>(x, y, w);
    finalize_kernel<<<1, 1>>>(out);
}

// round 6
// speedup vs baseline: 1.4779x; 1.4779x over previous
#include <cuda_runtime.h>

// Problem constants
#define DZ 64
#define HH 512
#define WW 512
#define PAD 5                    // window 11 -> half 5
#define TILE_H 32                // rows per block (smaller -> more blocks/occupancy)
#define NT 256                   // threads per block (8 warps)
#define G 2                      // columns per thread  (NT*G == WW)
#define ROWTILES (HH / TILE_H)   // 16
#define SH_W (WW + 2 * PAD + 2)  // 524, small pad

#define C1F 1.0e-4f      // 0.01^2
#define C2F 9.0e-4f      // 0.03^2

__device__ double g_accum;

__global__ void zero_accum_kernel() { g_accum = 0.0; }

__device__ __forceinline__ float ssim_from_sums(float sx, float sy, float sxx,
                                                float syy, float sxy, float wv) {
    float mx  = sx  * wv;
    float my  = sy  * wv;
    float ex2 = sxx * wv;
    float ey2 = syy * wv;
    float exy = sxy * wv;
    float mx2 = mx * mx;
    float my2 = my * my;
    float mxy = mx * my;
    float sgx  = ex2 - mx2;
    float sgy  = ey2 - my2;
    float sgxy = exy - mxy;
    float num = (2.0f * mxy + C1F) * (2.0f * sgxy + C2F);
    float den = (mx2 + my2 + C1F) * (sgx + sgy + C2F);
    return __fdividef(num, den);
}

__global__ __launch_bounds__(NT)
void ssim_kernel(const float* __restrict__ X, const float* __restrict__ Y,
                 const float* __restrict__ Wd) {
    // Double-buffered per-row exchange of vertical sums.
    // vsh4[b][idx] = (sum_x, sum_y, sum_x2, sum_y2) for column (idx-PAD)
    // vsh1[b][idx] = sum_xy
    __shared__ float4 vsh4[2][SH_W];
    __shared__ float  vsh1[2][SH_W];
    __shared__ float  redbuf[NT / 32];

    const int tid  = threadIdx.x;
    const int z    = blockIdx.x / ROWTILES;
    const int row0 = (blockIdx.x % ROWTILES) * TILE_H;

    const float* Xz = X + (size_t)z * HH * WW;
    const float* Yz = Y + (size_t)z * HH * WW;
    const float  wv = Wd[0];   // uniform window weight (1/121)

    // Zero the halo columns of both buffers once.
    if (tid < PAD) {
        #pragma unroll
        for (int b = 0; b < 2; ++b) {
            vsh4[b][tid]            = make_float4(0.f, 0.f, 0.f, 0.f);
            vsh1[b][tid]            = 0.f;
            vsh4[b][PAD + WW + tid] = make_float4(0.f, 0.f, 0.f, 0.f);
            vsh1[b][PAD + WW + tid] = 0.f;
        }
    }
    // (visibility guaranteed by the first __syncthreads inside the row loop)

    const int c0 = tid * G;   // first column owned by this thread

    // Vertical sliding sums for the 5 channels, 2 columns each (float2 lanes).
    float2 vs0 = make_float2(0.f, 0.f);  // sum x
    float2 vs1 = vs0;                    // sum y
    float2 vs2 = vs0;                    // sum x^2
    float2 vs3 = vs0;                    // sum y^2
    float2 vs4 = vs0;                    // sum x*y

    // Prologue: accumulate input rows [row0-5, row0+4]
    #pragma unroll 1
    for (int rr = row0 - PAD; rr < row0 + PAD; ++rr) {
        if (rr < 0 || rr >= HH) continue;
        float2 xv = *reinterpret_cast<const float2*>(Xz + rr * WW + c0);
        float2 yv = *reinterpret_cast<const float2*>(Yz + rr * WW + c0);
        vs0.x += xv.x;      vs0.y += xv.y;
        vs1.x += yv.x;      vs1.y += yv.y;
        vs2.x += xv.x*xv.x; vs2.y += xv.y*xv.y;
        vs3.x += yv.x*yv.x; vs3.y += yv.y*yv.y;
        vs4.x += xv.x*yv.x; vs4.y += xv.y*yv.y;
    }

    float partial = 0.0f;
    int buf = 0;

    #pragma unroll 1
    for (int r = row0; r < row0 + TILE_H; ++r, buf ^= 1) {
        // Slide vertical window: add row r+5; subtract row r-6, but ONLY if
        // that row was actually accumulated (the prologue starts at row0-5,
        // so at r == row0 nothing leaves the window).
        int rn = r + PAD;
        if (rn < HH) {
            float2 xv = *reinterpret_cast<const float2*>(Xz + rn * WW + c0);
            float2 yv = *reinterpret_cast<const float2*>(Yz + rn * WW + c0);
            vs0.x += xv.x;      vs0.y += xv.y;
            vs1.x += yv.x;      vs1.y += yv.y;
            vs2.x += xv.x*xv.x; vs2.y += xv.y*xv.y;
            vs3.x += yv.x*yv.x; vs3.y += yv.y*yv.y;
            vs4.x += xv.x*yv.x; vs4.y += xv.y*yv.y;
        }
        int ro = r - PAD - 1;
        if (r > row0 && ro >= 0) {
            float2 xv = *reinterpret_cast<const float2*>(Xz + ro * WW + c0);
            float2 yv = *reinterpret_cast<const float2*>(Yz + ro * WW + c0);
            vs0.x -= xv.x;      vs0.y -= xv.y;
            vs1.x -= yv.x;      vs1.y -= yv.y;
            vs2.x -= xv.x*xv.x; vs2.y -= xv.y*xv.y;
            vs3.x -= yv.x*yv.x; vs3.y -= yv.y*yv.y;
            vs4.x -= xv.x*yv.x; vs4.y -= xv.y*yv.y;
        }

        // Publish vertical sums (AoS transpose: per column float4 + float).
        int base = PAD + c0;
        vsh4[buf][base + 0] = make_float4(vs0.x, vs1.x, vs2.x, vs3.x);
        vsh1[buf][base + 0] = vs4.x;
        vsh4[buf][base + 1] = make_float4(vs0.y, vs1.y, vs2.y, vs3.y);
        vsh1[buf][base + 1] = vs4.y;

        __syncthreads();   // single barrier per row (double-buffered)

        // Horizontal 11-sum for column c0, then slide for c0+1.
        // Column c is stored at index c+PAD, so output col c0 reads idx c0..c0+10.
        float4 h  = make_float4(0.f, 0.f, 0.f, 0.f);
        float  h1 = 0.f;
        float4 k4_0;
        float  k1_0;
        #pragma unroll
        for (int k = 0; k < 11; ++k) {
            float4 f  = vsh4[buf][c0 + k];
            float  f1 = vsh1[buf][c0 + k];
            if (k == 0) { k4_0 = f; k1_0 = f1; }
            h.x += f.x; h.y += f.y; h.z += f.z; h.w += f.w;
            h1  += f1;
        }
        partial += ssim_from_sums(h.x, h.y, h.z, h.w, h1, wv);

        {
            float4 f  = vsh4[buf][c0 + 11];
            float  f1 = vsh1[buf][c0 + 11];
            h.x += f.x - k4_0.x;
            h.y += f.y - k4_0.y;
            h.z += f.z - k4_0.z;
            h.w += f.w - k4_0.w;
            h1  += f1  - k1_0;
            partial += ssim_from_sums(h.x, h.y, h.z, h.w, h1, wv);
        }
        // no second barrier: next iteration writes the other buffer
    }

    // Block reduction of partial SSIM sums.
    #pragma unroll
    for (int off = 16; off > 0; off >>= 1)
        partial += __shfl_xor_sync(0xFFFFFFFFu, partial, off);
    if ((tid & 31) == 0) redbuf[tid >> 5] = partial;
    __syncthreads();
    if (tid == 0) {
        float s = 0.f;
        #pragma unroll
        for (int i = 0; i < NT / 32; ++i) s += redbuf[i];
        atomicAdd(&g_accum, (double)s);
    }
}

__global__ void finalize_kernel(float* out) {
    out[0] = (float)(1.0 - g_accum / (double)((size_t)DZ * HH * WW));
}

extern "C" void kernel_launch(void* const* d_in, const int* in_sizes, int n_in,
                              void* d_out, int out_size) {
    const float* x = (const float*)d_in[0];
    const float* y = (const float*)d_in[1];
    const float* w = (const float*)d_in[2];
    float* out = (float*)d_out;

    zero_accum_kernel<<<1, 1>>>();
    ssim_kernel<<<DZ * ROWTILES, NT>>>(x, y, w);
    finalize_kernel<<<1, 1>>>(out);
}

// round 10
// speedup vs baseline: 3.1146x; 2.1075x over previous
#include <cuda_runtime.h>

#define DZ 64
#define HH 512
#define WW 512
#define PAD 5
#define TILE_H 32
#define NT 128                          // 4 warps per block
#define NSTRIP 3
#define ROWTILES (HH / TILE_H)          // 16
#define TOTAL_WARPS (DZ * ROWTILES * NSTRIP)   // 3072
#define NBLOCKS (TOTAL_WARPS / (NT/32))        // 768

// SSIM constants folded into raw-sum space (w = 1/121 cancels as w^4):
//   C1S = C1 * 121^2, C2S = C2 * 121^2
#define C1S 1.4641f
#define C2S 13.1769f

__device__ float g_partials[NBLOCKS];

// Vertical sliding-sum update for one input row (add or subtract).
template <int SGN>
__device__ __forceinline__ void vupdate(float vs[5][6],
                                        const float* __restrict__ xrow,
                                        const float* __restrict__ yrow,
                                        int cb) {
    float xr[6], yr[6];
    #pragma unroll
    for (int k = 0; k < 3; ++k) {
        int c = cb + 2 * k;
        bool ok = ((unsigned)c < (unsigned)WW);   // pairs never straddle 0/512
        float2 xv = ok ? *reinterpret_cast<const float2*>(xrow + c)
                       : make_float2(0.f, 0.f);
        float2 yv = ok ? *reinterpret_cast<const float2*>(yrow + c)
                       : make_float2(0.f, 0.f);
        xr[2*k] = xv.x; xr[2*k+1] = xv.y;
        yr[2*k] = yv.x; yr[2*k+1] = yv.y;
    }
    #pragma unroll
    for (int j = 0; j < 6; ++j) {
        if (SGN > 0) {
            vs[0][j] += xr[j];
            vs[1][j] += yr[j];
            vs[2][j] = fmaf(xr[j], xr[j], vs[2][j]);
            vs[3][j] = fmaf(yr[j], yr[j], vs[3][j]);
            vs[4][j] = fmaf(xr[j], yr[j], vs[4][j]);
        } else {
            vs[0][j] -= xr[j];
            vs[1][j] -= yr[j];
            vs[2][j] = fmaf(-xr[j], xr[j], vs[2][j]);
            vs[3][j] = fmaf(-yr[j], yr[j], vs[3][j]);
            vs[4][j] = fmaf(-xr[j], yr[j], vs[4][j]);
        }
    }
}

__global__ __launch_bounds__(NT)
void ssim_kernel(const float* __restrict__ X, const float* __restrict__ Y) {
    const int wid  = threadIdx.x >> 5;
    const int lane = threadIdx.x & 31;
    const int gw   = blockIdx.x * (NT / 32) + wid;

    const int s = gw % NSTRIP;          // column strip 0..2
    const int t = gw / NSTRIP;          // (z, rowtile)
    const int z = t >> 4;               // t / ROWTILES
    const int row0 = (t & (ROWTILES - 1)) * TILE_H;

    // Strip geometry: outputs [Ostart,Oend); warp computes vsums for 192
    // columns starting at V0 (covers all needed 11-tap windows + halo).
    const int Ostart = (s == 0) ? 0   : (s == 1 ? 172 : 342);
    const int Oend   = (s == 0) ? 172 : (s == 1 ? 342 : 512);
    const int V0     = (s == 2) ? 336 : Ostart - 8;

    const int cb = V0 + lane * 6;       // first vsum column of this lane (even)
    const float* __restrict__ Xz = X + (size_t)z * HH * WW;
    const float* __restrict__ Yz = Y + (size_t)z * HH * WW;

    // Vertical sliding sums: 5 channels (x, y, x^2, y^2, xy) x 6 columns.
    float vs[5][6];
    #pragma unroll
    for (int ch = 0; ch < 5; ++ch)
        #pragma unroll
        for (int j = 0; j < 6; ++j) vs[ch][j] = 0.f;

    // Prologue: rows [row0-5, row0+4] clamped to the image.
    #pragma unroll 1
    for (int rr = row0 - PAD; rr < row0 + PAD; ++rr) {
        if (rr < 0 || rr >= HH) continue;
        vupdate<+1>(vs, Xz + (size_t)rr * WW, Yz + (size_t)rr * WW, cb);
    }

    float partial = 0.f;

    #pragma unroll 1
    for (int r = row0; r < row0 + TILE_H; ++r) {
        int rn = r + PAD;
        if (rn < HH)
            vupdate<+1>(vs, Xz + (size_t)rn * WW, Yz + (size_t)rn * WW, cb);
        int ro = r - PAD - 1;
        if (r > row0 && ro >= 0)
            vupdate<-1>(vs, Xz + (size_t)ro * WW, Yz + (size_t)ro * WW, cb);

        // Horizontal 11-tap sums via warp shuffles (no shared memory).
        // win[16] covers columns cb-5 .. cb+10 for 6 outputs cb..cb+5.
        float Hs[5][6];
        #pragma unroll
        for (int ch = 0; ch < 5; ++ch) {
            float win[16];
            #pragma unroll
            for (int k = 0; k < 5; ++k)
                win[k] = __shfl_up_sync(0xFFFFFFFFu, vs[ch][k + 1], 1);
            #pragma unroll
            for (int j = 0; j < 6; ++j) win[5 + j] = vs[ch][j];
            #pragma unroll
            for (int k = 0; k < 5; ++k)
                win[11 + k] = __shfl_down_sync(0xFFFFFFFFu, vs[ch][k], 1);

            float h = 0.f;
            #pragma unroll
            for (int k = 0; k < 11; ++k) h += win[k];
            Hs[ch][0] = h;
            #pragma unroll
            for (int j = 1; j < 6; ++j) {
                h += win[10 + j] - win[j - 1];
                Hs[ch][j] = h;
            }
        }

        // SSIM in raw-sum space (scale factor w^4 cancels between num/den).
        #pragma unroll
        for (int j = 0; j < 6; ++j) {
            float Sx  = Hs[0][j], Sy  = Hs[1][j];
            float Sxx = Hs[2][j], Syy = Hs[3][j], Sxy = Hs[4][j];
            float P  = Sx * Sy;
            float Q  = fmaf(Sx, Sx, Sy * Sy);
            float n1 = fmaf(2.f, P, C1S);
            float n2 = fmaf(-2.f, P, fmaf(242.f, Sxy, C2S));
            float d1 = Q + C1S;
            float d2 = fmaf(121.f, Sxx + Syy, C2S - Q);
            float v  = __fdividef(n1 * n2, d1 * d2);
            int c = cb + j;
            if (c >= Ostart && c < Oend) partial += v;
        }
    }

    // Warp reduce, then one partial per block (no atomics).
    #pragma unroll
    for (int off = 16; off > 0; off >>= 1)
        partial += __shfl_xor_sync(0xFFFFFFFFu, partial, off);
    __shared__ float wsum[NT / 32];
    if (lane == 0) wsum[wid] = partial;
    __syncthreads();
    if (threadIdx.x == 0)
        g_partials[blockIdx.x] = wsum[0] + wsum[1] + wsum[2] + wsum[3];
}

__global__ void finalize_kernel(float* out) {
    __shared__ double sh[256];
    double s = 0.0;
    for (int i = threadIdx.x; i < NBLOCKS; i += 256)
        s += (double)g_partials[i];
    sh[threadIdx.x] = s;
    __syncthreads();
    for (int st = 128; st > 0; st >>= 1) {
        if (threadIdx.x < st) sh[threadIdx.x] += sh[threadIdx.x + st];
        __syncthreads();
    }
    if (threadIdx.x == 0)
        out[0] = (float)(1.0 - sh[0] / (double)((size_t)DZ * HH * WW));
}

extern "C" void kernel_launch(void* const* d_in, const int* in_sizes, int n_in,
                              void* d_out, int out_size) {
    const float* x = (const float*)d_in[0];
    const float* y = (const float*)d_in[1];
    float* out = (float*)d_out;

    ssim_kernel<<<NBLOCKS, NT>>>(x, y);
    finalize_kernel<<<1, 256>>>(out);
}